// round 2
// baseline (speedup 1.0000x reference)
#include <cuda_runtime.h>
#include <cuda_bf16.h>

// Problem sizes (fixed by the reference: B=4, L=512, D=256)
#define B 4
#define L 512
#define D 256
#define R_SIZE (B*L*D)        // 524288 floats (r)
#define A_SIZE (B*L*L)        // 1048576 floats (alpha)

#define TILE 64               // i/j tile for scores kernel
#define NT   (L/TILE)         // 8 tiles per dim
#define NPAIR (NT*(NT+1)/2)   // 36 upper-tri tile pairs per batch
#define SH_STRIDE 260         // padded row stride, multiple of 4 (float4 LDS),
                              // 260 % 32 == 4 -> conflict-free for our patterns

// 4 MB scratch for the pre-softmax scores
__device__ float g_scores[B*L*L];

__device__ __forceinline__ float tanh_approx(float x) {
    float y;
    asm("tanh.approx.f32 %0, %1;" : "=f"(y) : "f"(x));
    return y;
}

// ---------------------------------------------------------------------------
// Kernel 1: scores[b,i,j] = sum_d tanh(H[b,i,d]+H[b,j,d])*w[d]
// (bias dropped: softmax is shift-invariant, and only (r, alpha) are outputs)
// Symmetric => compute upper-triangle 64x64 tiles only, mirror on write.
// Grid: B*NPAIR = 144 blocks, 256 threads. Each thread: 4x4 micro-tile,
// d-loop processes 4 dims per iteration via float4 shared loads.
// ---------------------------------------------------------------------------
__global__ void __launch_bounds__(256)
scores_kernel(const float* __restrict__ H,
              const float* __restrict__ w) {
    extern __shared__ float sm[];
    float* sHi = sm;                        // TILE * SH_STRIDE
    float* sHj = sm + TILE * SH_STRIDE;     // TILE * SH_STRIDE
    float* sW  = sm + 2 * TILE * SH_STRIDE; // D

    const int blk = blockIdx.x;
    const int b   = blk / NPAIR;
    int p = blk % NPAIR;
    int ti = 0, rowlen = NT;
    while (p >= rowlen) { p -= rowlen; ++ti; --rowlen; }
    const int tj = ti + p;
    const int i0 = ti * TILE;
    const int j0 = tj * TILE;

    const int tid = threadIdx.x;
    const float* Hb = H + (size_t)b * L * D;

    if (tid < D / 4)
        *reinterpret_cast<float4*>(sW + 4 * tid) =
            reinterpret_cast<const float4*>(w)[tid];

    // Load Hi / Hj tiles (TILE x D) via float4 global + float4 smem stores.
    const int F4_PER_TILE = TILE * D / 4;   // 4096
    #pragma unroll
    for (int it = 0; it < F4_PER_TILE / 256; ++it) {
        int e = tid + 256 * it;
        int row = e >> 6;          // D/4 = 64 float4 per row
        int c4  = e & 63;
        float4 v = *reinterpret_cast<const float4*>(Hb + (size_t)(i0 + row) * D + 4 * c4);
        *reinterpret_cast<float4*>(sHi + row * SH_STRIDE + 4 * c4) = v;
    }
    #pragma unroll
    for (int it = 0; it < F4_PER_TILE / 256; ++it) {
        int e = tid + 256 * it;
        int row = e >> 6;
        int c4  = e & 63;
        float4 v = *reinterpret_cast<const float4*>(Hb + (size_t)(j0 + row) * D + 4 * c4);
        *reinterpret_cast<float4*>(sHj + row * SH_STRIDE + 4 * c4) = v;
    }
    __syncthreads();

    const int tx = tid & 15;
    const int ty = tid >> 4;

    float acc[4][4];
    #pragma unroll
    for (int m = 0; m < 4; ++m)
        #pragma unroll
        for (int n = 0; n < 4; ++n) acc[m][n] = 0.0f;

    for (int d4 = 0; d4 < D / 4; ++d4) {
        float4 wv = *reinterpret_cast<const float4*>(sW + 4 * d4);
        float4 hi[4], hj[4];
        #pragma unroll
        for (int m = 0; m < 4; ++m)
            hi[m] = *reinterpret_cast<const float4*>(sHi + (ty + 16 * m) * SH_STRIDE + 4 * d4);
        #pragma unroll
        for (int n = 0; n < 4; ++n)
            hj[n] = *reinterpret_cast<const float4*>(sHj + (tx + 16 * n) * SH_STRIDE + 4 * d4);
        #pragma unroll
        for (int m = 0; m < 4; ++m)
            #pragma unroll
            for (int n = 0; n < 4; ++n) {
                float s = acc[m][n];
                s = fmaf(tanh_approx(hi[m].x + hj[n].x), wv.x, s);
                s = fmaf(tanh_approx(hi[m].y + hj[n].y), wv.y, s);
                s = fmaf(tanh_approx(hi[m].z + hj[n].z), wv.z, s);
                s = fmaf(tanh_approx(hi[m].w + hj[n].w), wv.w, s);
                acc[m][n] = s;
            }
    }

    const int mirror = (ti != tj);
    #pragma unroll
    for (int m = 0; m < 4; ++m) {
        int gi = i0 + ty + 16 * m;
        #pragma unroll
        for (int n = 0; n < 4; ++n) {
            int gj = j0 + tx + 16 * n;
            float v = acc[m][n];
            g_scores[((size_t)b * L + gi) * L + gj] = v;
            if (mirror)
                g_scores[((size_t)b * L + gj) * L + gi] = v;
        }
    }
}

// ---------------------------------------------------------------------------
// Kernel 2: row softmax of g_scores -> alpha (written directly into d_out).
// Grid: B*L = 2048 blocks, 256 threads, 2 elems/thread.
// ---------------------------------------------------------------------------
__global__ void softmax_kernel(float* __restrict__ out_alpha) {
    const int row = blockIdx.x;              // 0 .. B*L-1
    const int tid = threadIdx.x;
    const float* srow = g_scores + (size_t)row * L;

    float v0 = srow[tid];
    float v1 = srow[tid + 256];

    __shared__ float red_max[8];
    __shared__ float red_sum[8];
    const int wid = tid >> 5, lane = tid & 31;

    float m = fmaxf(v0, v1);
    #pragma unroll
    for (int o = 16; o; o >>= 1) m = fmaxf(m, __shfl_xor_sync(0xffffffffu, m, o));
    if (lane == 0) red_max[wid] = m;
    __syncthreads();
    float M = red_max[0];
    #pragma unroll
    for (int i = 1; i < 8; ++i) M = fmaxf(M, red_max[i]);

    float e0 = __expf(v0 - M);
    float e1 = __expf(v1 - M);

    float s = e0 + e1;
    #pragma unroll
    for (int o = 16; o; o >>= 1) s += __shfl_xor_sync(0xffffffffu, s, o);
    if (lane == 0) red_sum[wid] = s;
    __syncthreads();
    float S = red_sum[0];
    #pragma unroll
    for (int i = 1; i < 8; ++i) S += red_sum[i];

    float inv = 1.0f / S;
    out_alpha[(size_t)row * L + tid]       = e0 * inv;
    out_alpha[(size_t)row * L + tid + 256] = e1 * inv;
}

// ---------------------------------------------------------------------------
// Kernel 3: r[b] = alpha[b] (LxL) @ H[b] (LxD).
// 64x64 tile, BK=32, double-buffered smem, float4 everywhere.
// Grid: (D/64, L/64, B) = (4, 8, 4) = 128 blocks, 256 threads, 4x4 tiles.
// ---------------------------------------------------------------------------
#define BK 32
#define AS_STRIDE 36   // pad for float4-aligned rows
#define BS_STRIDE 68

__global__ void __launch_bounds__(256)
gemm_kernel(const float* __restrict__ alpha,
            const float* __restrict__ H,
            float* __restrict__ r) {
    const int b  = blockIdx.z;
    const int i0 = blockIdx.y * 64;
    const int d0 = blockIdx.x * 64;

    const float* A  = alpha + (size_t)b * L * L;
    const float* Bm = H     + (size_t)b * L * D;
    float*       C  = r     + (size_t)b * L * D;

    __shared__ float As[2][64 * AS_STRIDE];   // [i][k]
    __shared__ float Bs[2][BK * BS_STRIDE];   // [k][d]

    const int tid = threadIdx.x;
    const int tx = tid & 15, ty = tid >> 4;

    // loader indices
    const int a_i  = tid >> 3;        // 0..31 (row within half)
    const int a_k4 = tid & 7;         // 0..7  (float4 within 32-k chunk)
    const int b_k  = tid >> 4;        // 0..15 (k row within half)
    const int b_d4 = tid & 15;        // 0..15 (float4 within 64-d row)

    float acc[4][4];
    #pragma unroll
    for (int m = 0; m < 4; ++m)
        #pragma unroll
        for (int n = 0; n < 4; ++n) acc[m][n] = 0.0f;

    // prologue: load tile 0
    {
        #pragma unroll
        for (int h = 0; h < 2; ++h) {
            int ai = a_i + 32 * h;
            float4 v = *reinterpret_cast<const float4*>(A + (size_t)(i0 + ai) * L + 4 * a_k4);
            *reinterpret_cast<float4*>(&As[0][ai * AS_STRIDE + 4 * a_k4]) = v;
        }
        #pragma unroll
        for (int h = 0; h < 2; ++h) {
            int bk = b_k + 16 * h;
            float4 v = *reinterpret_cast<const float4*>(Bm + (size_t)bk * D + d0 + 4 * b_d4);
            *reinterpret_cast<float4*>(&Bs[0][bk * BS_STRIDE + 4 * b_d4]) = v;
        }
    }
    __syncthreads();

    #pragma unroll 1
    for (int kt = 0; kt < L / BK; ++kt) {
        const int cur = kt & 1, nxt = cur ^ 1;

        // prefetch next tile into registers
        float4 pa[2], pb[2];
        if (kt + 1 < L / BK) {
            int k0n = (kt + 1) * BK;
            #pragma unroll
            for (int h = 0; h < 2; ++h) {
                int ai = a_i + 32 * h;
                pa[h] = *reinterpret_cast<const float4*>(A + (size_t)(i0 + ai) * L + k0n + 4 * a_k4);
            }
            #pragma unroll
            for (int h = 0; h < 2; ++h) {
                int bk = b_k + 16 * h;
                pb[h] = *reinterpret_cast<const float4*>(Bm + (size_t)(k0n + bk) * D + d0 + 4 * b_d4);
            }
        }

        // compute on current tile
        #pragma unroll
        for (int kk = 0; kk < BK; ++kk) {
            float a[4];
            #pragma unroll
            for (int m = 0; m < 4; ++m)
                a[m] = As[cur][(ty * 4 + m) * AS_STRIDE + kk];
            float4 bv = *reinterpret_cast<const float4*>(&Bs[cur][kk * BS_STRIDE + tx * 4]);
            #pragma unroll
            for (int m = 0; m < 4; ++m) {
                acc[m][0] = fmaf(a[m], bv.x, acc[m][0]);
                acc[m][1] = fmaf(a[m], bv.y, acc[m][1]);
                acc[m][2] = fmaf(a[m], bv.z, acc[m][2]);
                acc[m][3] = fmaf(a[m], bv.w, acc[m][3]);
            }
        }

        // store prefetched tile into the other buffer
        if (kt + 1 < L / BK) {
            #pragma unroll
            for (int h = 0; h < 2; ++h) {
                int ai = a_i + 32 * h;
                *reinterpret_cast<float4*>(&As[nxt][ai * AS_STRIDE + 4 * a_k4]) = pa[h];
            }
            #pragma unroll
            for (int h = 0; h < 2; ++h) {
                int bk = b_k + 16 * h;
                *reinterpret_cast<float4*>(&Bs[nxt][bk * BS_STRIDE + 4 * b_d4]) = pb[h];
            }
        }
        __syncthreads();
    }

    #pragma unroll
    for (int m = 0; m < 4; ++m) {
        int gi = i0 + ty * 4 + m;
        float4 v = make_float4(acc[m][0], acc[m][1], acc[m][2], acc[m][3]);
        *reinterpret_cast<float4*>(C + (size_t)gi * D + d0 + tx * 4) = v;
    }
}

// ---------------------------------------------------------------------------
extern "C" void kernel_launch(void* const* d_in, const int* in_sizes, int n_in,
                              void* d_out, int out_size) {
    const float* H    = (const float*)d_in[0];
    const float* w    = (const float*)d_in[1];

    float* out   = (float*)d_out;
    float* r     = out;            // first R_SIZE floats
    float* alpha = out + R_SIZE;   // next A_SIZE floats

    const int smem_bytes = (2 * TILE * SH_STRIDE + D) * (int)sizeof(float);
    cudaFuncSetAttribute(scores_kernel,
                         cudaFuncAttributeMaxDynamicSharedMemorySize, smem_bytes);

    scores_kernel<<<B * NPAIR, 256, smem_bytes>>>(H, w);
    softmax_kernel<<<B * L, 256>>>(alpha);
    gemm_kernel<<<dim3(D / 64, L / 64, B), 256>>>(alpha, H, r);
}

// round 4
// speedup vs baseline: 1.3667x; 1.3667x over previous
#include <cuda_runtime.h>
#include <cuda_bf16.h>

// Problem sizes (fixed by the reference: B=4, L=512, D=256)
#define B 4
#define L 512
#define D 256
#define R_SIZE (B*L*D)        // 524288 floats (r)
#define A_SIZE (B*L*L)        // 1048576 floats (alpha)

#define TILE 64               // i/j tile for scores kernel
#define NT   (L/TILE)         // 8 tiles per dim
#define NPAIR (NT*(NT+1)/2)   // 36 upper-tri tile pairs per batch
#define SH_STRIDE 257         // padded row stride (bank-conflict free)

// 4 MB scratch for the pre-softmax scores
__device__ float g_scores[B*L*L];

__device__ __forceinline__ float tanh_approx(float x) {
    float y;
    asm("tanh.approx.f32 %0, %1;" : "=f"(y) : "f"(x));
    return y;
}

// ---------------------------------------------------------------------------
// Kernel 1: scores[b,i,j] = sum_d tanh(H[b,i,d]+H[b,j,d])*w[d]
// (bias dropped: softmax is shift-invariant; only (r, alpha) are outputs)
// Symmetric => compute upper-triangle 64x64 tiles only, mirror on write.
// EXACT round-1 structure (measured 42.9us, ~84% of MUFU floor).
// ---------------------------------------------------------------------------
__global__ void __launch_bounds__(256)
scores_kernel(const float* __restrict__ H,
              const float* __restrict__ w) {
    extern __shared__ float sm[];
    float* sHi = sm;                        // TILE * SH_STRIDE
    float* sHj = sm + TILE * SH_STRIDE;     // TILE * SH_STRIDE
    float* sW  = sm + 2 * TILE * SH_STRIDE; // D

    const int blk = blockIdx.x;
    const int b   = blk / NPAIR;
    int p = blk % NPAIR;
    int ti = 0, rowlen = NT;
    while (p >= rowlen) { p -= rowlen; ++ti; --rowlen; }
    const int tj = ti + p;
    const int i0 = ti * TILE;
    const int j0 = tj * TILE;

    const int tid = threadIdx.x;
    const float* Hb = H + (size_t)b * L * D;

    if (tid < D) sW[tid] = w[tid];

    const int F4_PER_TILE = TILE * D / 4;   // 4096
    #pragma unroll
    for (int it = 0; it < F4_PER_TILE / 256; ++it) {
        int e = tid + 256 * it;
        int row = e >> 6;          // D/4 = 64 float4 per row
        int c4  = e & 63;
        float4 v = *reinterpret_cast<const float4*>(Hb + (size_t)(i0 + row) * D + 4 * c4);
        float* dst = sHi + row * SH_STRIDE + 4 * c4;
        dst[0] = v.x; dst[1] = v.y; dst[2] = v.z; dst[3] = v.w;
    }
    #pragma unroll
    for (int it = 0; it < F4_PER_TILE / 256; ++it) {
        int e = tid + 256 * it;
        int row = e >> 6;
        int c4  = e & 63;
        float4 v = *reinterpret_cast<const float4*>(Hb + (size_t)(j0 + row) * D + 4 * c4);
        float* dst = sHj + row * SH_STRIDE + 4 * c4;
        dst[0] = v.x; dst[1] = v.y; dst[2] = v.z; dst[3] = v.w;
    }
    __syncthreads();

    const int tx = tid & 15;
    const int ty = tid >> 4;

    float acc[4][4];
    #pragma unroll
    for (int m = 0; m < 4; ++m)
        #pragma unroll
        for (int n = 0; n < 4; ++n) acc[m][n] = 0.0f;

    #pragma unroll 2
    for (int d = 0; d < D; ++d) {
        float wd = sW[d];
        float hi[4], hj[4];
        #pragma unroll
        for (int m = 0; m < 4; ++m) hi[m] = sHi[(ty + 16 * m) * SH_STRIDE + d];
        #pragma unroll
        for (int n = 0; n < 4; ++n) hj[n] = sHj[(tx + 16 * n) * SH_STRIDE + d];
        #pragma unroll
        for (int m = 0; m < 4; ++m)
            #pragma unroll
            for (int n = 0; n < 4; ++n)
                acc[m][n] = fmaf(tanh_approx(hi[m] + hj[n]), wd, acc[m][n]);
    }

    const int mirror = (ti != tj);
    #pragma unroll
    for (int m = 0; m < 4; ++m) {
        int gi = i0 + ty + 16 * m;
        #pragma unroll
        for (int n = 0; n < 4; ++n) {
            int gj = j0 + tx + 16 * n;
            float v = acc[m][n];
            g_scores[((size_t)b * L + gi) * L + gj] = v;
            if (mirror)
                g_scores[((size_t)b * L + gj) * L + gi] = v;
        }
    }
}

// ---------------------------------------------------------------------------
// Kernel 2: fused softmax + GEMM.
// Per CTA: (b, 32-row i-block, 128-col d-half).
//   1) load scores[i0:i0+32, :] (32x512) into smem
//   2) in-place softmax numerator (exp(v - max)); 1/sum kept per-row
//   3) d-half 0 writes alpha = exp * invS to d_out
//   4) r[i-block, d-half] = (exp @ H) * invS, double-buffered smem GEMM
// Grid: (2, 16, 4) = 128 CTAs, 256 threads, 2x8 micro-tile per thread.
// ---------------------------------------------------------------------------
#define SS   516   // score-block row stride (floats), %4==0 for float4
#define BSTR 132   // Bs row stride

__global__ void __launch_bounds__(256)
fused_softmax_gemm(const float* __restrict__ H,
                   float* __restrict__ out_alpha,
                   float* __restrict__ out_r) {
    extern __shared__ float sm[];
    float* S    = sm;                     // 32 * SS
    float* Bs   = sm + 32 * SS;           // 2 * 32 * BSTR
    float* invS = Bs + 2 * 32 * BSTR;     // 32

    const int bx = blockIdx.x;            // d-half: 0 or 1
    const int i0 = blockIdx.y * 32;
    const int b  = blockIdx.z;
    const int d0 = bx * 128;
    const int tid = threadIdx.x;

    const float* Hb = H + (size_t)b * L * D;
    const float* Sg = g_scores + ((size_t)b * L + i0) * L;

    // Phase 1: scores block -> smem (32x512, float4)
    #pragma unroll
    for (int it = 0; it < 16; ++it) {
        int e = tid + 256 * it;           // 4096 float4
        int row = e >> 7, c4 = e & 127;
        float4 v = *reinterpret_cast<const float4*>(Sg + (size_t)row * L + 4 * c4);
        *reinterpret_cast<float4*>(S + row * SS + 4 * c4) = v;
    }
    // Prologue: Bs tile 0 (k rows 0..31)
    #pragma unroll
    for (int it = 0; it < 4; ++it) {
        int e = tid + 256 * it;           // 1024 float4
        int kk = e >> 5, c = e & 31;
        float4 v = *reinterpret_cast<const float4*>(Hb + (size_t)kk * D + d0 + 4 * c);
        *reinterpret_cast<float4*>(Bs + kk * BSTR + 4 * c) = v;
    }
    __syncthreads();

    // Phase 2: softmax numerators; 8 lanes per row, 64 cols each
    {
        const int row = tid >> 3, sub = tid & 7;
        float* Srow = S + row * SS + sub * 64;

        float mx = -1e30f;
        #pragma unroll
        for (int c = 0; c < 16; ++c) {
            float4 v = *reinterpret_cast<const float4*>(Srow + 4 * c);
            mx = fmaxf(mx, fmaxf(fmaxf(v.x, v.y), fmaxf(v.z, v.w)));
        }
        #pragma unroll
        for (int o = 4; o; o >>= 1)
            mx = fmaxf(mx, __shfl_xor_sync(0xffffffffu, mx, o, 8));

        float s = 0.0f;
        #pragma unroll
        for (int c = 0; c < 16; ++c) {
            float4 v = *reinterpret_cast<float4*>(Srow + 4 * c);
            v.x = __expf(v.x - mx); v.y = __expf(v.y - mx);
            v.z = __expf(v.z - mx); v.w = __expf(v.w - mx);
            s += (v.x + v.y) + (v.z + v.w);
            *reinterpret_cast<float4*>(Srow + 4 * c) = v;
        }
        #pragma unroll
        for (int o = 4; o; o >>= 1)
            s += __shfl_xor_sync(0xffffffffu, s, o, 8);
        if (sub == 0) invS[row] = 1.0f / s;
    }
    __syncthreads();

    // Phase 3: alpha output (only d-half 0 CTAs)
    if (bx == 0) {
        const int row = tid >> 3, sub = tid & 7;
        const float is = invS[row];
        const float* Srow = S + row * SS + sub * 64;
        float* Arow = out_alpha + ((size_t)b * L + i0 + row) * L + sub * 64;
        #pragma unroll
        for (int c = 0; c < 16; ++c) {
            float4 v = *reinterpret_cast<const float4*>(Srow + 4 * c);
            v.x *= is; v.y *= is; v.z *= is; v.w *= is;
            *reinterpret_cast<float4*>(Arow + 4 * c) = v;
        }
    }

    // Phase 4: GEMM  r[32 x 128] = S(32x512) @ H(512x128 slice), double-buffered
    const int tx = tid & 15;              // d micro-index (4-wide, two halves)
    const int ty = tid >> 4;              // i micro-index (2 rows)

    float acc[2][8];
    #pragma unroll
    for (int m = 0; m < 2; ++m)
        #pragma unroll
        for (int n = 0; n < 8; ++n) acc[m][n] = 0.0f;

    #pragma unroll 1
    for (int kt = 0; kt < 16; ++kt) {
        const int cur = kt & 1, nxt = cur ^ 1;

        float4 pf[4];
        if (kt < 15) {
            const int k0n = (kt + 1) * 32;
            #pragma unroll
            for (int it = 0; it < 4; ++it) {
                int e = tid + 256 * it;
                int kk = e >> 5, c = e & 31;
                pf[it] = *reinterpret_cast<const float4*>(Hb + (size_t)(k0n + kk) * D + d0 + 4 * c);
            }
        }

        const float* Bc = Bs + cur * 32 * BSTR;
        const int kb = kt * 32;
        #pragma unroll
        for (int kk = 0; kk < 32; ++kk) {
            float a0 = S[(2 * ty)     * SS + kb + kk];
            float a1 = S[(2 * ty + 1) * SS + kb + kk];
            float4 b0 = *reinterpret_cast<const float4*>(Bc + kk * BSTR + 4 * tx);
            float4 b1 = *reinterpret_cast<const float4*>(Bc + kk * BSTR + 64 + 4 * tx);
            acc[0][0] = fmaf(a0, b0.x, acc[0][0]);
            acc[0][1] = fmaf(a0, b0.y, acc[0][1]);
            acc[0][2] = fmaf(a0, b0.z, acc[0][2]);
            acc[0][3] = fmaf(a0, b0.w, acc[0][3]);
            acc[0][4] = fmaf(a0, b1.x, acc[0][4]);
            acc[0][5] = fmaf(a0, b1.y, acc[0][5]);
            acc[0][6] = fmaf(a0, b1.z, acc[0][6]);
            acc[0][7] = fmaf(a0, b1.w, acc[0][7]);
            acc[1][0] = fmaf(a1, b0.x, acc[1][0]);
            acc[1][1] = fmaf(a1, b0.y, acc[1][1]);
            acc[1][2] = fmaf(a1, b0.z, acc[1][2]);
            acc[1][3] = fmaf(a1, b0.w, acc[1][3]);
            acc[1][4] = fmaf(a1, b1.x, acc[1][4]);
            acc[1][5] = fmaf(a1, b1.y, acc[1][5]);
            acc[1][6] = fmaf(a1, b1.z, acc[1][6]);
            acc[1][7] = fmaf(a1, b1.w, acc[1][7]);
        }

        if (kt < 15) {
            float* Bn = Bs + nxt * 32 * BSTR;
            #pragma unroll
            for (int it = 0; it < 4; ++it) {
                int e = tid + 256 * it;
                int kk = e >> 5, c = e & 31;
                *reinterpret_cast<float4*>(Bn + kk * BSTR + 4 * c) = pf[it];
            }
        }
        __syncthreads();
    }

    // Epilogue: scale by invS, write r
    {
        const float is0 = invS[2 * ty];
        const float is1 = invS[2 * ty + 1];
        float* C0 = out_r + ((size_t)b * L + i0 + 2 * ty)     * D + d0;
        float* C1 = out_r + ((size_t)b * L + i0 + 2 * ty + 1) * D + d0;
        float4 v;
        v = make_float4(acc[0][0] * is0, acc[0][1] * is0, acc[0][2] * is0, acc[0][3] * is0);
        *reinterpret_cast<float4*>(C0 + 4 * tx) = v;
        v = make_float4(acc[0][4] * is0, acc[0][5] * is0, acc[0][6] * is0, acc[0][7] * is0);
        *reinterpret_cast<float4*>(C0 + 64 + 4 * tx) = v;
        v = make_float4(acc[1][0] * is1, acc[1][1] * is1, acc[1][2] * is1, acc[1][3] * is1);
        *reinterpret_cast<float4*>(C1 + 4 * tx) = v;
        v = make_float4(acc[1][4] * is1, acc[1][5] * is1, acc[1][6] * is1, acc[1][7] * is1);
        *reinterpret_cast<float4*>(C1 + 64 + 4 * tx) = v;
    }
}

// ---------------------------------------------------------------------------
extern "C" void kernel_launch(void* const* d_in, const int* in_sizes, int n_in,
                              void* d_out, int out_size) {
    const float* H = (const float*)d_in[0];
    const float* w = (const float*)d_in[1];

    float* out   = (float*)d_out;
    float* r     = out;            // first R_SIZE floats
    float* alpha = out + R_SIZE;   // next A_SIZE floats

    const int smem1 = (2 * TILE * SH_STRIDE + D) * (int)sizeof(float);
    cudaFuncSetAttribute(scores_kernel,
                         cudaFuncAttributeMaxDynamicSharedMemorySize, smem1);

    const int smem2 = (32 * SS + 2 * 32 * BSTR + 32) * (int)sizeof(float);
    cudaFuncSetAttribute(fused_softmax_gemm,
                         cudaFuncAttributeMaxDynamicSharedMemorySize, smem2);

    scores_kernel<<<B * NPAIR, 256, smem1>>>(H, w);
    fused_softmax_gemm<<<dim3(2, L / 32, B), 256, smem2>>>(H, alpha, r);
}

// round 5
// speedup vs baseline: 1.4071x; 1.0296x over previous
#include <cuda_runtime.h>
#include <cuda_bf16.h>
#include <cuda_fp16.h>

// Problem sizes (fixed by the reference: B=4, L=512, D=256)
#define B 4
#define L 512
#define D 256
#define D2 (D/2)              // 128 half2 pairs
#define R_SIZE (B*L*D)        // 524288 floats (r)
#define A_SIZE (B*L*L)        // 1048576 floats (alpha)

#define TILE 64               // i/j tile for scores kernel
#define NT   (L/TILE)         // 8 tiles per dim
#define NPAIR (NT*(NT+1)/2)   // 36 upper-tri tile pairs per batch
#define SH2  130              // half2 row stride (130%32==2 -> conflict-free)

// 4 MB scratch for the pre-softmax scores
__device__ float g_scores[B*L*L];

__device__ __forceinline__ __half2 tanh2_approx(__half2 x) {
    unsigned xin = *reinterpret_cast<unsigned*>(&x);
    unsigned yout;
    asm("tanh.approx.f16x2 %0, %1;" : "=r"(yout) : "r"(xin));
    return *reinterpret_cast<__half2*>(&yout);
}

// ---------------------------------------------------------------------------
// Kernel 1: scores[b,i,j] = sum_d tanh(H[b,i,d]+H[b,j,d])*w[d]
// (bias dropped: softmax is shift-invariant; only (r, alpha) are outputs)
// Symmetric => upper-triangle 64x64 tiles only, mirror on write.
// f16x2 path: H tiles stored as half2 (d-pairs); one tanh.approx.f16x2 covers
// two d's -> MUFU instruction count halved vs fp32 tanh. Accumulate in fp32.
// smem ~67KB -> 2 CTAs/SM.
// ---------------------------------------------------------------------------
__global__ void __launch_bounds__(256)
scores_kernel(const float* __restrict__ H,
              const float* __restrict__ w) {
    extern __shared__ __align__(16) unsigned smraw[];
    __half2* sHi = reinterpret_cast<__half2*>(smraw);           // 64 * SH2
    __half2* sHj = sHi + 64 * SH2;                              // 64 * SH2
    float2*  sW2 = reinterpret_cast<float2*>(sHj + 64 * SH2);   // D2

    const int blk = blockIdx.x;
    const int b   = blk / NPAIR;
    int p = blk % NPAIR;
    int ti = 0, rowlen = NT;
    while (p >= rowlen) { p -= rowlen; ++ti; --rowlen; }
    const int tj = ti + p;
    const int i0 = ti * TILE;
    const int j0 = tj * TILE;

    const int tid = threadIdx.x;
    const float* Hb = H + (size_t)b * L * D;

    if (tid < D2) sW2[tid] = reinterpret_cast<const float2*>(w)[tid];

    // Load tiles: f32 float4 from GMEM, convert to 2x half2, store to smem.
    #pragma unroll
    for (int it = 0; it < 16; ++it) {
        int e = tid + 256 * it;          // 4096 float4 per tile
        int row = e >> 6;                // 64 float4 per row
        int c4  = e & 63;
        float4 v = *reinterpret_cast<const float4*>(Hb + (size_t)(i0 + row) * D + 4 * c4);
        sHi[row * SH2 + 2 * c4]     = __floats2half2_rn(v.x, v.y);
        sHi[row * SH2 + 2 * c4 + 1] = __floats2half2_rn(v.z, v.w);
    }
    #pragma unroll
    for (int it = 0; it < 16; ++it) {
        int e = tid + 256 * it;
        int row = e >> 6;
        int c4  = e & 63;
        float4 v = *reinterpret_cast<const float4*>(Hb + (size_t)(j0 + row) * D + 4 * c4);
        sHj[row * SH2 + 2 * c4]     = __floats2half2_rn(v.x, v.y);
        sHj[row * SH2 + 2 * c4 + 1] = __floats2half2_rn(v.z, v.w);
    }
    __syncthreads();

    const int tx = tid & 15;
    const int ty = tid >> 4;

    float acc[4][4];
    #pragma unroll
    for (int m = 0; m < 4; ++m)
        #pragma unroll
        for (int n = 0; n < 4; ++n) acc[m][n] = 0.0f;

    #pragma unroll 2
    for (int dp = 0; dp < D2; ++dp) {
        float2 wv = sW2[dp];
        __half2 hi[4], hj[4];
        #pragma unroll
        for (int m = 0; m < 4; ++m) hi[m] = sHi[(ty + 16 * m) * SH2 + dp];
        #pragma unroll
        for (int n = 0; n < 4; ++n) hj[n] = sHj[(tx + 16 * n) * SH2 + dp];
        #pragma unroll
        for (int m = 0; m < 4; ++m)
            #pragma unroll
            for (int n = 0; n < 4; ++n) {
                __half2 t = tanh2_approx(__hadd2(hi[m], hj[n]));
                float2 f = __half22float2(t);
                acc[m][n] = fmaf(f.y, wv.y, fmaf(f.x, wv.x, acc[m][n]));
            }
    }

    const int mirror = (ti != tj);
    #pragma unroll
    for (int m = 0; m < 4; ++m) {
        int gi = i0 + ty + 16 * m;
        #pragma unroll
        for (int n = 0; n < 4; ++n) {
            int gj = j0 + tx + 16 * n;
            float v = acc[m][n];
            g_scores[((size_t)b * L + gi) * L + gj] = v;
            if (mirror)
                g_scores[((size_t)b * L + gj) * L + gi] = v;
        }
    }
}

// ---------------------------------------------------------------------------
// Kernel 2: warp-per-row softmax, shfl-only (no __syncthreads).
// Grid: 256 CTAs x 256 thr = 2048 warps = B*L rows. 16 elems/lane.
// Writes normalized alpha directly to d_out.
// ---------------------------------------------------------------------------
__global__ void __launch_bounds__(256)
softmax_kernel(float* __restrict__ out_alpha) {
    const int lane = threadIdx.x & 31;
    const int row  = blockIdx.x * 8 + (threadIdx.x >> 5);   // 0..2047
    const float4* S4 = reinterpret_cast<const float4*>(g_scores + (size_t)row * L);

    float4 v[4];
    #pragma unroll
    for (int k = 0; k < 4; ++k) v[k] = S4[lane + 32 * k];

    float mx = -1e30f;
    #pragma unroll
    for (int k = 0; k < 4; ++k)
        mx = fmaxf(mx, fmaxf(fmaxf(v[k].x, v[k].y), fmaxf(v[k].z, v[k].w)));
    #pragma unroll
    for (int o = 16; o; o >>= 1) mx = fmaxf(mx, __shfl_xor_sync(0xffffffffu, mx, o));

    float s = 0.0f;
    #pragma unroll
    for (int k = 0; k < 4; ++k) {
        v[k].x = __expf(v[k].x - mx); v[k].y = __expf(v[k].y - mx);
        v[k].z = __expf(v[k].z - mx); v[k].w = __expf(v[k].w - mx);
        s += (v[k].x + v[k].y) + (v[k].z + v[k].w);
    }
    #pragma unroll
    for (int o = 16; o; o >>= 1) s += __shfl_xor_sync(0xffffffffu, s, o);
    const float inv = 1.0f / s;

    float4* A4 = reinterpret_cast<float4*>(out_alpha + (size_t)row * L);
    #pragma unroll
    for (int k = 0; k < 4; ++k) {
        float4 o4 = make_float4(v[k].x * inv, v[k].y * inv, v[k].z * inv, v[k].w * inv);
        A4[lane + 32 * k] = o4;
    }
}

// ---------------------------------------------------------------------------
// Kernel 3: r[b] = alpha[b] (LxL) @ H[b] (LxD).
// 32x64 tiles (i x d), BK=32, 128 threads, 256 CTAs, double-buffered smem,
// float4 LDS on both operands (As stored k-major). ~27KB smem -> high occ.
// Grid: (D/64, L/32, B) = (4, 16, 4).
// ---------------------------------------------------------------------------
__global__ void __launch_bounds__(128)
gemm_kernel(const float* __restrict__ alpha,
            const float* __restrict__ H,
            float* __restrict__ r) {
    __shared__ float As[2][32][36];   // [buf][k][i]
    __shared__ float Bs[2][32][68];   // [buf][k][d]

    const int b  = blockIdx.z;
    const int i0 = blockIdx.y * 32;
    const int d0 = blockIdx.x * 64;

    const float* A  = alpha + (size_t)b * L * L;
    const float* Bm = H     + (size_t)b * L * D;
    float*       C  = r     + (size_t)b * L * D;

    const int tid = threadIdx.x;
    const int tx = tid & 15;          // d group (4 floats)
    const int ty = tid >> 4;          // i group (4 rows), 0..7

    float acc[4][4];
    #pragma unroll
    for (int m = 0; m < 4; ++m)
        #pragma unroll
        for (int n = 0; n < 4; ++n) acc[m][n] = 0.0f;

    // prologue: fill buffer 0 (k0 = 0)
    #pragma unroll
    for (int t = 0; t < 2; ++t) {
        int e = tid + 128 * t;        // 256 float4 of A tile (32i x 32k)
        int ai = e >> 3, ak4 = e & 7;
        float4 v = *reinterpret_cast<const float4*>(A + (size_t)(i0 + ai) * L + 4 * ak4);
        As[0][4 * ak4 + 0][ai] = v.x;
        As[0][4 * ak4 + 1][ai] = v.y;
        As[0][4 * ak4 + 2][ai] = v.z;
        As[0][4 * ak4 + 3][ai] = v.w;
    }
    #pragma unroll
    for (int t = 0; t < 4; ++t) {
        int e = tid + 128 * t;        // 512 float4 of B tile (32k x 64d)
        int bk = e >> 4, bd4 = e & 15;
        float4 v = *reinterpret_cast<const float4*>(Bm + (size_t)bk * D + d0 + 4 * bd4);
        *reinterpret_cast<float4*>(&Bs[0][bk][4 * bd4]) = v;
    }
    __syncthreads();

    #pragma unroll 1
    for (int kt = 0; kt < 16; ++kt) {
        const int cur = kt & 1, nxt = cur ^ 1;

        float4 pa[2], pb[4];
        if (kt < 15) {
            const int k0n = (kt + 1) * 32;
            #pragma unroll
            for (int t = 0; t < 2; ++t) {
                int e = tid + 128 * t;
                int ai = e >> 3, ak4 = e & 7;
                pa[t] = *reinterpret_cast<const float4*>(A + (size_t)(i0 + ai) * L + k0n + 4 * ak4);
            }
            #pragma unroll
            for (int t = 0; t < 4; ++t) {
                int e = tid + 128 * t;
                int bk = e >> 4, bd4 = e & 15;
                pb[t] = *reinterpret_cast<const float4*>(Bm + (size_t)(k0n + bk) * D + d0 + 4 * bd4);
            }
        }

        #pragma unroll
        for (int kk = 0; kk < 32; ++kk) {
            float4 a = *reinterpret_cast<const float4*>(&As[cur][kk][ty * 4]);
            float4 bv = *reinterpret_cast<const float4*>(&Bs[cur][kk][tx * 4]);
            acc[0][0] = fmaf(a.x, bv.x, acc[0][0]);
            acc[0][1] = fmaf(a.x, bv.y, acc[0][1]);
            acc[0][2] = fmaf(a.x, bv.z, acc[0][2]);
            acc[0][3] = fmaf(a.x, bv.w, acc[0][3]);
            acc[1][0] = fmaf(a.y, bv.x, acc[1][0]);
            acc[1][1] = fmaf(a.y, bv.y, acc[1][1]);
            acc[1][2] = fmaf(a.y, bv.z, acc[1][2]);
            acc[1][3] = fmaf(a.y, bv.w, acc[1][3]);
            acc[2][0] = fmaf(a.z, bv.x, acc[2][0]);
            acc[2][1] = fmaf(a.z, bv.y, acc[2][1]);
            acc[2][2] = fmaf(a.z, bv.z, acc[2][2]);
            acc[2][3] = fmaf(a.z, bv.w, acc[2][3]);
            acc[3][0] = fmaf(a.w, bv.x, acc[3][0]);
            acc[3][1] = fmaf(a.w, bv.y, acc[3][1]);
            acc[3][2] = fmaf(a.w, bv.z, acc[3][2]);
            acc[3][3] = fmaf(a.w, bv.w, acc[3][3]);
        }

        if (kt < 15) {
            #pragma unroll
            for (int t = 0; t < 2; ++t) {
                int e = tid + 128 * t;
                int ai = e >> 3, ak4 = e & 7;
                As[nxt][4 * ak4 + 0][ai] = pa[t].x;
                As[nxt][4 * ak4 + 1][ai] = pa[t].y;
                As[nxt][4 * ak4 + 2][ai] = pa[t].z;
                As[nxt][4 * ak4 + 3][ai] = pa[t].w;
            }
            #pragma unroll
            for (int t = 0; t < 4; ++t) {
                int e = tid + 128 * t;
                int bk = e >> 4, bd4 = e & 15;
                *reinterpret_cast<float4*>(&Bs[nxt][bk][4 * bd4]) = pb[t];
            }
        }
        __syncthreads();
    }

    #pragma unroll
    for (int m = 0; m < 4; ++m) {
        int gi = i0 + ty * 4 + m;
        float4 v = make_float4(acc[m][0], acc[m][1], acc[m][2], acc[m][3]);
        *reinterpret_cast<float4*>(C + (size_t)gi * D + d0 + 4 * tx) = v;
    }
}

// ---------------------------------------------------------------------------
extern "C" void kernel_launch(void* const* d_in, const int* in_sizes, int n_in,
                              void* d_out, int out_size) {
    const float* H = (const float*)d_in[0];
    const float* w = (const float*)d_in[1];

    float* out   = (float*)d_out;
    float* r     = out;            // first R_SIZE floats
    float* alpha = out + R_SIZE;   // next A_SIZE floats

    const int smem1 = (2 * 64 * SH2) * (int)sizeof(__half2) + D2 * (int)sizeof(float2);
    cudaFuncSetAttribute(scores_kernel,
                         cudaFuncAttributeMaxDynamicSharedMemorySize, smem1);

    scores_kernel<<<B * NPAIR, 256, smem1>>>(H, w);
    softmax_kernel<<<256, 256>>>(alpha);
    gemm_kernel<<<dim3(D / 64, L / 32, B), 128>>>(alpha, H, r);
}

// round 6
// speedup vs baseline: 1.7021x; 1.2097x over previous
#include <cuda_runtime.h>
#include <cuda_bf16.h>
#include <cuda_fp16.h>

// Problem sizes (fixed by the reference: B=4, L=512, D=256)
#define B 4
#define L 512
#define D 256
#define D2 (D/2)              // 128 half2 pairs
#define R_SIZE (B*L*D)        // 524288 floats (r)
#define A_SIZE (B*L*L)        // 1048576 floats (alpha)

#define TILE 64               // i/j tile for scores kernel
#define NT   (L/TILE)         // 8 tiles per dim
#define NPAIR (NT*(NT+1)/2)   // 36 upper-tri tile pairs per batch
#define SH2  130              // half2 row stride (130%32==2 -> conflict-free)

// 4 MB scratch for the pre-softmax scores
__device__ float g_scores[B*L*L];

__device__ __forceinline__ __half2 tanh2_approx(__half2 x) {
    unsigned xin = *reinterpret_cast<unsigned*>(&x);
    unsigned yout;
    asm("tanh.approx.f16x2 %0, %1;" : "=r"(yout) : "r"(xin));
    return *reinterpret_cast<__half2*>(&yout);
}

// ---------------------------------------------------------------------------
// Kernel 1: scores[b,i,j] = sum_d tanh(H[b,i,d]+H[b,j,d])*w[d]
// (bias dropped: softmax is shift-invariant; only (r, alpha) are outputs)
// Symmetric => upper-triangle 64x64 tiles only, mirror on write.
// 512 threads (2x4 micro-tile). Inner loop is pure half2:
//   HADD2 -> tanh.approx.f16x2 -> HFMA2(t, w2, acc2)
// acc2 flushed to fp32 every 4 d-pairs (keeps half rounding bounded).
// ---------------------------------------------------------------------------
__global__ void __launch_bounds__(512)
scores_kernel(const float* __restrict__ H,
              const float* __restrict__ w) {
    extern __shared__ __align__(16) unsigned smraw[];
    __half2* sHi = reinterpret_cast<__half2*>(smraw);           // 64 * SH2
    __half2* sHj = sHi + 64 * SH2;                              // 64 * SH2
    __half2* sWh = sHj + 64 * SH2;                              // D2

    const int blk = blockIdx.x;
    const int b   = blk / NPAIR;
    int p = blk % NPAIR;
    int ti = 0, rowlen = NT;
    while (p >= rowlen) { p -= rowlen; ++ti; --rowlen; }
    const int tj = ti + p;
    const int i0 = ti * TILE;
    const int j0 = tj * TILE;

    const int tid = threadIdx.x;
    const float* Hb = H + (size_t)b * L * D;

    if (tid < D2) {
        float2 wv = reinterpret_cast<const float2*>(w)[tid];
        sWh[tid] = __float22half2_rn(wv);
    }

    // Load tiles: f32 float4 from GMEM, convert to 2x half2, store to smem.
    #pragma unroll
    for (int it = 0; it < 8; ++it) {
        int e = tid + 512 * it;          // 4096 float4 per tile
        int row = e >> 6;                // 64 float4 per row
        int c4  = e & 63;
        float4 v = *reinterpret_cast<const float4*>(Hb + (size_t)(i0 + row) * D + 4 * c4);
        sHi[row * SH2 + 2 * c4]     = __floats2half2_rn(v.x, v.y);
        sHi[row * SH2 + 2 * c4 + 1] = __floats2half2_rn(v.z, v.w);
    }
    #pragma unroll
    for (int it = 0; it < 8; ++it) {
        int e = tid + 512 * it;
        int row = e >> 6;
        int c4  = e & 63;
        float4 v = *reinterpret_cast<const float4*>(Hb + (size_t)(j0 + row) * D + 4 * c4);
        sHj[row * SH2 + 2 * c4]     = __floats2half2_rn(v.x, v.y);
        sHj[row * SH2 + 2 * c4 + 1] = __floats2half2_rn(v.z, v.w);
    }
    __syncthreads();

    const int tx = tid & 15;     // col group: cols tx + 16n, n=0..3
    const int ty = tid >> 4;     // row group: rows ty + 32m, m=0..1 (0..31)

    float accf[2][4];
    #pragma unroll
    for (int m = 0; m < 2; ++m)
        #pragma unroll
        for (int n = 0; n < 4; ++n) accf[m][n] = 0.0f;

    #pragma unroll 2
    for (int c = 0; c < D2 / 4; ++c) {      // 32 chunks of 4 d-pairs
        __half2 acc2[2][4];
        #pragma unroll
        for (int m = 0; m < 2; ++m)
            #pragma unroll
            for (int n = 0; n < 4; ++n) acc2[m][n] = __halves2half2(__ushort_as_half(0), __ushort_as_half(0));

        #pragma unroll
        for (int u = 0; u < 4; ++u) {
            const int dp = 4 * c + u;
            const __half2 w2 = sWh[dp];
            __half2 hi[2], hj[4];
            #pragma unroll
            for (int m = 0; m < 2; ++m) hi[m] = sHi[(ty + 32 * m) * SH2 + dp];
            #pragma unroll
            for (int n = 0; n < 4; ++n) hj[n] = sHj[(tx + 16 * n) * SH2 + dp];
            #pragma unroll
            for (int m = 0; m < 2; ++m)
                #pragma unroll
                for (int n = 0; n < 4; ++n) {
                    __half2 t = tanh2_approx(__hadd2(hi[m], hj[n]));
                    acc2[m][n] = __hfma2(t, w2, acc2[m][n]);
                }
        }

        #pragma unroll
        for (int m = 0; m < 2; ++m)
            #pragma unroll
            for (int n = 0; n < 4; ++n) {
                float2 f = __half22float2(acc2[m][n]);
                accf[m][n] += f.x + f.y;
            }
    }

    const int mirror = (ti != tj);
    #pragma unroll
    for (int m = 0; m < 2; ++m) {
        int gi = i0 + ty + 32 * m;
        #pragma unroll
        for (int n = 0; n < 4; ++n) {
            int gj = j0 + tx + 16 * n;
            float v = accf[m][n];
            g_scores[((size_t)b * L + gi) * L + gj] = v;
            if (mirror)
                g_scores[((size_t)b * L + gj) * L + gi] = v;
        }
    }
}

// ---------------------------------------------------------------------------
// Kernel 2: warp-per-row softmax, shfl-only (no __syncthreads).
// Grid: 256 CTAs x 256 thr = 2048 warps = B*L rows. 16 elems/lane.
// ---------------------------------------------------------------------------
__global__ void __launch_bounds__(256)
softmax_kernel(float* __restrict__ out_alpha) {
    const int lane = threadIdx.x & 31;
    const int row  = blockIdx.x * 8 + (threadIdx.x >> 5);   // 0..2047
    const float4* S4 = reinterpret_cast<const float4*>(g_scores + (size_t)row * L);

    float4 v[4];
    #pragma unroll
    for (int k = 0; k < 4; ++k) v[k] = S4[lane + 32 * k];

    float mx = -1e30f;
    #pragma unroll
    for (int k = 0; k < 4; ++k)
        mx = fmaxf(mx, fmaxf(fmaxf(v[k].x, v[k].y), fmaxf(v[k].z, v[k].w)));
    #pragma unroll
    for (int o = 16; o; o >>= 1) mx = fmaxf(mx, __shfl_xor_sync(0xffffffffu, mx, o));

    float s = 0.0f;
    #pragma unroll
    for (int k = 0; k < 4; ++k) {
        v[k].x = __expf(v[k].x - mx); v[k].y = __expf(v[k].y - mx);
        v[k].z = __expf(v[k].z - mx); v[k].w = __expf(v[k].w - mx);
        s += (v[k].x + v[k].y) + (v[k].z + v[k].w);
    }
    #pragma unroll
    for (int o = 16; o; o >>= 1) s += __shfl_xor_sync(0xffffffffu, s, o);
    const float inv = 1.0f / s;

    float4* A4 = reinterpret_cast<float4*>(out_alpha + (size_t)row * L);
    #pragma unroll
    for (int k = 0; k < 4; ++k) {
        float4 o4 = make_float4(v[k].x * inv, v[k].y * inv, v[k].z * inv, v[k].w * inv);
        A4[lane + 32 * k] = o4;
    }
}

// ---------------------------------------------------------------------------
// Kernel 3: r[b] = alpha[b] (LxL) @ H[b] (LxD).
// 32x64 tiles (i x d), BK=32, 128 threads, 256 CTAs, double-buffered smem.
// Grid: (D/64, L/32, B) = (4, 16, 4).
// ---------------------------------------------------------------------------
__global__ void __launch_bounds__(128)
gemm_kernel(const float* __restrict__ alpha,
            const float* __restrict__ H,
            float* __restrict__ r) {
    __shared__ float As[2][32][36];   // [buf][k][i]
    __shared__ float Bs[2][32][68];   // [buf][k][d]

    const int b  = blockIdx.z;
    const int i0 = blockIdx.y * 32;
    const int d0 = blockIdx.x * 64;

    const float* A  = alpha + (size_t)b * L * L;
    const float* Bm = H     + (size_t)b * L * D;
    float*       C  = r     + (size_t)b * L * D;

    const int tid = threadIdx.x;
    const int tx = tid & 15;          // d group (4 floats)
    const int ty = tid >> 4;          // i group (4 rows), 0..7

    float acc[4][4];
    #pragma unroll
    for (int m = 0; m < 4; ++m)
        #pragma unroll
        for (int n = 0; n < 4; ++n) acc[m][n] = 0.0f;

    // prologue: fill buffer 0 (k0 = 0)
    #pragma unroll
    for (int t = 0; t < 2; ++t) {
        int e = tid + 128 * t;        // 256 float4 of A tile (32i x 32k)
        int ai = e >> 3, ak4 = e & 7;
        float4 v = *reinterpret_cast<const float4*>(A + (size_t)(i0 + ai) * L + 4 * ak4);
        As[0][4 * ak4 + 0][ai] = v.x;
        As[0][4 * ak4 + 1][ai] = v.y;
        As[0][4 * ak4 + 2][ai] = v.z;
        As[0][4 * ak4 + 3][ai] = v.w;
    }
    #pragma unroll
    for (int t = 0; t < 4; ++t) {
        int e = tid + 128 * t;        // 512 float4 of B tile (32k x 64d)
        int bk = e >> 4, bd4 = e & 15;
        float4 v = *reinterpret_cast<const float4*>(Bm + (size_t)bk * D + d0 + 4 * bd4);
        *reinterpret_cast<float4*>(&Bs[0][bk][4 * bd4]) = v;
    }
    __syncthreads();

    #pragma unroll 1
    for (int kt = 0; kt < 16; ++kt) {
        const int cur = kt & 1, nxt = cur ^ 1;

        float4 pa[2], pb[4];
        if (kt < 15) {
            const int k0n = (kt + 1) * 32;
            #pragma unroll
            for (int t = 0; t < 2; ++t) {
                int e = tid + 128 * t;
                int ai = e >> 3, ak4 = e & 7;
                pa[t] = *reinterpret_cast<const float4*>(A + (size_t)(i0 + ai) * L + k0n + 4 * ak4);
            }
            #pragma unroll
            for (int t = 0; t < 4; ++t) {
                int e = tid + 128 * t;
                int bk = e >> 4, bd4 = e & 15;
                pb[t] = *reinterpret_cast<const float4*>(Bm + (size_t)(k0n + bk) * D + d0 + 4 * bd4);
            }
        }

        #pragma unroll
        for (int kk = 0; kk < 32; ++kk) {
            float4 a = *reinterpret_cast<const float4*>(&As[cur][kk][ty * 4]);
            float4 bv = *reinterpret_cast<const float4*>(&Bs[cur][kk][tx * 4]);
            acc[0][0] = fmaf(a.x, bv.x, acc[0][0]);
            acc[0][1] = fmaf(a.x, bv.y, acc[0][1]);
            acc[0][2] = fmaf(a.x, bv.z, acc[0][2]);
            acc[0][3] = fmaf(a.x, bv.w, acc[0][3]);
            acc[1][0] = fmaf(a.y, bv.x, acc[1][0]);
            acc[1][1] = fmaf(a.y, bv.y, acc[1][1]);
            acc[1][2] = fmaf(a.y, bv.z, acc[1][2]);
            acc[1][3] = fmaf(a.y, bv.w, acc[1][3]);
            acc[2][0] = fmaf(a.z, bv.x, acc[2][0]);
            acc[2][1] = fmaf(a.z, bv.y, acc[2][1]);
            acc[2][2] = fmaf(a.z, bv.z, acc[2][2]);
            acc[2][3] = fmaf(a.z, bv.w, acc[2][3]);
            acc[3][0] = fmaf(a.w, bv.x, acc[3][0]);
            acc[3][1] = fmaf(a.w, bv.y, acc[3][1]);
            acc[3][2] = fmaf(a.w, bv.z, acc[3][2]);
            acc[3][3] = fmaf(a.w, bv.w, acc[3][3]);
        }

        if (kt < 15) {
            #pragma unroll
            for (int t = 0; t < 2; ++t) {
                int e = tid + 128 * t;
                int ai = e >> 3, ak4 = e & 7;
                As[nxt][4 * ak4 + 0][ai] = pa[t].x;
                As[nxt][4 * ak4 + 1][ai] = pa[t].y;
                As[nxt][4 * ak4 + 2][ai] = pa[t].z;
                As[nxt][4 * ak4 + 3][ai] = pa[t].w;
            }
            #pragma unroll
            for (int t = 0; t < 4; ++t) {
                int e = tid + 128 * t;
                int bk = e >> 4, bd4 = e & 15;
                *reinterpret_cast<float4*>(&Bs[nxt][bk][4 * bd4]) = pb[t];
            }
        }
        __syncthreads();
    }

    #pragma unroll
    for (int m = 0; m < 4; ++m) {
        int gi = i0 + ty * 4 + m;
        float4 v = make_float4(acc[m][0], acc[m][1], acc[m][2], acc[m][3]);
        *reinterpret_cast<float4*>(C + (size_t)gi * D + d0 + 4 * tx) = v;
    }
}

// ---------------------------------------------------------------------------
extern "C" void kernel_launch(void* const* d_in, const int* in_sizes, int n_in,
                              void* d_out, int out_size) {
    const float* H = (const float*)d_in[0];
    const float* w = (const float*)d_in[1];

    float* out   = (float*)d_out;
    float* r     = out;            // first R_SIZE floats
    float* alpha = out + R_SIZE;   // next A_SIZE floats

    const int smem1 = (2 * 64 * SH2 + D2) * (int)sizeof(__half2);
    cudaFuncSetAttribute(scores_kernel,
                         cudaFuncAttributeMaxDynamicSharedMemorySize, smem1);

    scores_kernel<<<B * NPAIR, 512, smem1>>>(H, w);
    softmax_kernel<<<256, 256>>>(alpha);
    gemm_kernel<<<dim3(D / 64, L / 32, B), 128>>>(alpha, H, r);
}